// round 3
// baseline (speedup 1.0000x reference)
#include <cuda_runtime.h>
#include <cuda_bf16.h>
#include <math.h>

#define BB 32
#define TT 2048
#define DD 256
#define HH 128

// Scratch for input projection: xp0[t][b][h]
__device__ float g_xp0[(size_t)TT * BB * HH];

// tanh via MUFU.EX2 + MUFU.RCP: abs err ~1e-7, overflow-safe (e->0 => r->1)
__device__ __forceinline__ float fast_tanh(float x) {
    float ax = fabsf(x);
    float e  = __expf(-2.0f * ax);                 // in (0,1]
    float r  = __fdividef(1.0f - e, 1.0f + e);
    return copysignf(r, x);
}

// ---------------------------------------------------------------------------
// Kernel A (round-1 proven): xp0[t][b][j] = x[b][t][:].W_ih0[j][:] + biases
// One block per t. 256 threads; thread covers 4 j x 4 b register tile.
// ---------------------------------------------------------------------------
__global__ __launch_bounds__(256) void input_proj_kernel(
    const float* __restrict__ x,
    const float* __restrict__ W_ih0,
    const float* __restrict__ b_ih0,
    const float* __restrict__ b_hh0)
{
    __shared__ float xs[BB][64];        // [b][k-chunk]
    __shared__ float ws[64][HH];        // [k][j] transposed -> conflict-free

    const int t   = blockIdx.x;
    const int tid = threadIdx.x;
    const int jg  = (tid & 31) * 4;
    const int bg  = (tid >> 5) * 4;

    float acc[4][4];
#pragma unroll
    for (int i = 0; i < 4; i++)
#pragma unroll
        for (int k = 0; k < 4; k++) acc[i][k] = 0.f;

    for (int k0 = 0; k0 < DD; k0 += 64) {
        for (int i = tid; i < BB * 16; i += 256) {
            int b  = i >> 4;
            int kk = (i & 15) * 4;
            *(float4*)&xs[b][kk] =
                *(const float4*)&x[((size_t)b * TT + t) * DD + k0 + kk];
        }
        for (int i = tid; i < HH * 16; i += 256) {
            int j  = i >> 4;
            int kk = (i & 15) * 4;
            float4 w = *(const float4*)&W_ih0[(size_t)j * DD + k0 + kk];
            ws[kk + 0][j] = w.x;
            ws[kk + 1][j] = w.y;
            ws[kk + 2][j] = w.z;
            ws[kk + 3][j] = w.w;
        }
        __syncthreads();

#pragma unroll 16
        for (int k = 0; k < 64; k++) {
            float4 wv = *(const float4*)&ws[k][jg];
            float x0 = xs[bg + 0][k];
            float x1 = xs[bg + 1][k];
            float x2 = xs[bg + 2][k];
            float x3 = xs[bg + 3][k];
            acc[0][0] += wv.x * x0; acc[0][1] += wv.y * x0;
            acc[0][2] += wv.z * x0; acc[0][3] += wv.w * x0;
            acc[1][0] += wv.x * x1; acc[1][1] += wv.y * x1;
            acc[1][2] += wv.z * x1; acc[1][3] += wv.w * x1;
            acc[2][0] += wv.x * x2; acc[2][1] += wv.y * x2;
            acc[2][2] += wv.z * x2; acc[2][3] += wv.w * x2;
            acc[3][0] += wv.x * x3; acc[3][1] += wv.y * x3;
            acc[3][2] += wv.z * x3; acc[3][3] += wv.w * x3;
        }
        __syncthreads();
    }

#pragma unroll
    for (int jj = 0; jj < 4; jj++) {
        float bias = b_ih0[jg + jj] + b_hh0[jg + jj];
#pragma unroll
        for (int bb2 = 0; bb2 < 4; bb2++) {
            g_xp0[((size_t)t * BB + (bg + bb2)) * HH + jg + jj] = acc[bb2][jj] + bias;
        }
    }
}

// ---------------------------------------------------------------------------
// Kernel B: the recurrence. One CTA per batch (32 CTAs), 512 threads.
// tid = j*4 + c: j = tid>>2 in [0,128), c = tid&3 is a 32-wide k-chunk.
// Weight-stationary scalar float4 (96 regs/thread), quad-shuffle reductions,
// 2 barriers/step, fast tanh, double-buffered h0, bank-padded h layout
// (chunk cc starts at cc*36 -> the 4 per-quad float4 LDS addresses hit
// distinct banks).
// ---------------------------------------------------------------------------
__global__ void __launch_bounds__(512, 1) rnn_rec_kernel(
    const float* __restrict__ W_hh0,
    const float* __restrict__ W_ih1,
    const float* __restrict__ W_hh1,
    const float* __restrict__ b_ih1,
    const float* __restrict__ b_hh1,
    float* __restrict__ out)
{
    const int bidx = blockIdx.x;
    const int tid  = threadIdx.x;
    const int j    = tid >> 2;       // output index
    const int c    = tid & 3;        // k-chunk

    __shared__ __align__(16) float h0buf[2][4 * 36];
    __shared__ __align__(16) float h1buf[4 * 36];

    // register-stationary weights: chunk [c*32, c*32+32) of row j
    float4 w0[8], w1[8], w2[8];
    {
        const float4* p0 = (const float4*)&W_hh0[(size_t)j * HH + c * 32];
        const float4* p1 = (const float4*)&W_ih1[(size_t)j * HH + c * 32];
        const float4* p2 = (const float4*)&W_hh1[(size_t)j * HH + c * 32];
#pragma unroll
        for (int i = 0; i < 8; i++) { w0[i] = p0[i]; w1[i] = p1[i]; w2[i] = p2[i]; }
    }

    const int posj = (j >> 5) * 36 + (j & 31);   // padded position of h[j]
    const float biasj = b_ih1[j] + b_hh1[j];

    for (int i = tid; i < 4 * 36; i += 512) {
        h0buf[0][i] = 0.f;
        h0buf[1][i] = 0.f;
        h1buf[i]    = 0.f;
    }
    __syncthreads();

    const float* xpb  = g_xp0 + (size_t)bidx * HH + j;   // &xp[t][bidx][j]
    float*       outb = out + (size_t)bidx * TT * HH;

    float xpr = *xpb;                                     // t = 0
    xpb += (size_t)BB * HH;

    for (int t = 0; t < TT; t++) {
        const int p = t & 1;
        const float4* h0rd = (const float4*)&h0buf[p][c * 36];
        const float4* h1rd = (const float4*)&h1buf[c * 36];

        // ---- Phase A: partials of W_hh0.h0 and W_hh1.h1(prev) ----
        float a0a = 0.f, a0b = 0.f, a1a = 0.f, a1b = 0.f;
#pragma unroll
        for (int i = 0; i < 8; i++) {
            float4 h = h0rd[i];
            a0a += w0[i].x * h.x + w0[i].y * h.y;
            a0b += w0[i].z * h.z + w0[i].w * h.w;
            float4 g = h1rd[i];
            a1a += w2[i].x * g.x + w2[i].y * g.y;
            a1b += w2[i].z * g.z + w2[i].w * g.w;
        }
        float a0 = a0a + a0b;
        float a1 = a1a + a1b;
        a0 += __shfl_xor_sync(0xFFFFFFFFu, a0, 1);
        a0 += __shfl_xor_sync(0xFFFFFFFFu, a0, 2);
        a1 += __shfl_xor_sync(0xFFFFFFFFu, a1, 1);
        a1 += __shfl_xor_sync(0xFFFFFFFFu, a1, 2);

        float h0n = fast_tanh(xpr + a0);
        h0buf[1 - p][posj] = h0n;            // write NEW buffer (no race)
        float s1 = a1 + biasj;               // stays in register across barrier

        if (t + 1 < TT) {                    // prefetch next xp
            xpr = *xpb;
            xpb += (size_t)BB * HH;
        }

        __syncthreads();

        // ---- Phase B: partials of W_ih1.h0n ----
        const float4* h0nw = (const float4*)&h0buf[1 - p][c * 36];
        float b0a = 0.f, b0b = 0.f;
#pragma unroll
        for (int i = 0; i < 8; i++) {
            float4 h = h0nw[i];
            b0a += w1[i].x * h.x + w1[i].y * h.y;
            b0b += w1[i].z * h.z + w1[i].w * h.w;
        }
        float b0 = b0a + b0b;
        b0 += __shfl_xor_sync(0xFFFFFFFFu, b0, 1);
        b0 += __shfl_xor_sync(0xFFFFFFFFu, b0, 2);

        float h1n = fast_tanh(s1 + b0);
        h1buf[posj] = h1n;
        if (c == 0)
            outb[(size_t)t * HH + j] = h1n;

        __syncthreads();
    }
}

// ---------------------------------------------------------------------------
extern "C" void kernel_launch(void* const* d_in, const int* in_sizes, int n_in,
                              void* d_out, int out_size)
{
    const float* x     = (const float*)d_in[0];
    const float* W_ih0 = (const float*)d_in[1];
    const float* W_hh0 = (const float*)d_in[2];
    const float* b_ih0 = (const float*)d_in[3];
    const float* b_hh0 = (const float*)d_in[4];
    const float* W_ih1 = (const float*)d_in[5];
    const float* W_hh1 = (const float*)d_in[6];
    const float* b_ih1 = (const float*)d_in[7];
    const float* b_hh1 = (const float*)d_in[8];
    float* out = (float*)d_out;

    input_proj_kernel<<<TT, 256>>>(x, W_ih0, b_ih0, b_hh0);
    rnn_rec_kernel<<<BB, 512>>>(W_hh0, W_ih1, W_hh1, b_ih1, b_hh1, out);
}